// round 8
// baseline (speedup 1.0000x reference)
#include <cuda_runtime.h>
#include <cstdint>

#define NJ 50
#define EDIM 192
#define NJP 56           // padded codes: j = js + 8*jj, js in [0,8), jj in [0,7)
#define ETS 64           // Et row stride in floats ([k][j], j slot = code id, 50..63 zero)
#define NWARP 8
#define NTHREADS 256
#define RPT 6            // rows per thread
#define ROWS_PER_WARP 24 // 4 g-groups * 6
#define ROWS_PER_BLOCK 192

__device__ double g_loss_sum;     // zero-init at module load
__device__ unsigned int g_done;

static __device__ __forceinline__ unsigned long long pack2(float lo, float hi) {
    unsigned long long r;
    asm("mov.b64 %0, {%1, %2};" : "=l"(r) : "f"(lo), "f"(hi));
    return r;
}
static __device__ __forceinline__ unsigned long long pack2s(float v) {
    unsigned long long r;
    asm("mov.b64 %0, {%1, %1};" : "=l"(r) : "f"(v));
    return r;
}
static __device__ __forceinline__ void unpack2(unsigned long long v, float& lo, float& hi) {
    asm("mov.b64 {%0, %1}, %2;" : "=f"(lo), "=f"(hi) : "l"(v));
}
// Packed dual fp32 FMA (FFMA2)
static __device__ __forceinline__ unsigned long long fma2(unsigned long long a,
                                                          unsigned long long b,
                                                          unsigned long long c) {
    unsigned long long d;
    asm("fma.rn.f32x2 %0, %1, %2, %3;" : "=l"(d) : "l"(a), "l"(b), "l"(c));
    return d;
}

// lane = (g<<3)|js : js in [0,8) code split (codes j = js + 8*jj), g in [0,4).
// Thread rows: base + g + 4*i, i=0..5 (6 rows/thread, 24 rows/warp).
// acc f32x2 packs a ROW PAIR (2pr, 2pr+1); e is broadcast (pack2s of one LDS.32).
__global__ void __launch_bounds__(NTHREADS, 2) vq_kernel(
        const float* __restrict__ x, const float* __restrict__ e,
        float* __restrict__ out, int n) {
    __shared__ float Et[EDIM * ETS];   // Et[k*64 + j] = e[j][k]; j>=50 zero
    __shared__ float see[NJP];
    __shared__ int   bjsh[ROWS_PER_BLOCK];
    __shared__ float wred[NWARP];

    const int tid = threadIdx.x;
    const int wid = tid >> 5;
    const int lane = tid & 31;
    const int js = lane & 7;
    const int g = lane >> 3;

    // ---- init: zero Et, fill [k][j] transpose, see (+inf pads) ----
    for (int i = tid; i < EDIM * ETS; i += NTHREADS) Et[i] = 0.f;
    __syncthreads();
    for (int i = tid; i < NJ * EDIM; i += NTHREADS) {
        int j = i / EDIM, k = i - j * EDIM;        // e[j][k] coalesced read
        Et[k * ETS + j] = e[i];
    }
    if (tid < NJP) {
        float s = 3.402823466e38f;
        if (tid < NJ) {
            s = 0.f;
            const float* ej = e + (size_t)tid * EDIM;
            #pragma unroll 4
            for (int k = 0; k < EDIM; ++k) { float v = __ldg(ej + k); s = fmaf(v, v, s); }
        }
        see[tid] = s;
    }
    __syncthreads();

    const int tile_base = blockIdx.x * ROWS_PER_BLOCK;
    const int warpbase = wid * ROWS_PER_WARP;
    int rows[RPT];
    #pragma unroll
    for (int i = 0; i < RPT; ++i) {
        int r = tile_base + warpbase + g + 4 * i;
        rows[i] = (r < n) ? r : (n - 1);
    }

    // ---- accumulate: acc[jj][pr] = dots of code (js+8jj) for rows (2pr, 2pr+1) ----
    unsigned long long acc[7][3];
    unsigned long long ss0[3], ss1[3];             // ||x||^2: x,z -> ss0 ; y,w -> ss1
    #pragma unroll
    for (int jj = 0; jj < 7; ++jj)
        #pragma unroll
        for (int pr = 0; pr < 3; ++pr) acc[jj][pr] = 0ULL;
    #pragma unroll
    for (int pr = 0; pr < 3; ++pr) { ss0[pr] = 0ULL; ss1[pr] = 0ULL; }

    const float4* x4 = reinterpret_cast<const float4*>(x);

    #pragma unroll 1
    for (int kq = 0; kq < EDIM / 4; ++kq) {
        float4 xv[RPT];
        #pragma unroll
        for (int i = 0; i < RPT; ++i)
            xv[i] = __ldg(x4 + (size_t)rows[i] * 48 + kq);

        #pragma unroll
        for (int c = 0; c < 4; ++c) {
            const int k = kq * 4 + c;
            float a0, a1, a2, a3, a4, a5;
            if (c == 0)      { a0=xv[0].x; a1=xv[1].x; a2=xv[2].x; a3=xv[3].x; a4=xv[4].x; a5=xv[5].x; }
            else if (c == 1) { a0=xv[0].y; a1=xv[1].y; a2=xv[2].y; a3=xv[3].y; a4=xv[4].y; a5=xv[5].y; }
            else if (c == 2) { a0=xv[0].z; a1=xv[1].z; a2=xv[2].z; a3=xv[3].z; a4=xv[4].z; a5=xv[5].z; }
            else             { a0=xv[0].w; a1=xv[1].w; a2=xv[2].w; a3=xv[3].w; a4=xv[4].w; a5=xv[5].w; }
            const unsigned long long xp0 = pack2(a0, a1);
            const unsigned long long xp1 = pack2(a2, a3);
            const unsigned long long xp2 = pack2(a4, a5);
            // ||x||^2: comps x,z -> ss0 ; y,w -> ss1 (per-row order == R2 chain)
            if ((c & 1) == 0) {
                ss0[0] = fma2(xp0, xp0, ss0[0]);
                ss0[1] = fma2(xp1, xp1, ss0[1]);
                ss0[2] = fma2(xp2, xp2, ss0[2]);
            } else {
                ss1[0] = fma2(xp0, xp0, ss1[0]);
                ss1[1] = fma2(xp1, xp1, ss1[1]);
                ss1[2] = fma2(xp2, xp2, ss1[2]);
            }
            const float* ek = &Et[k * ETS + js];
            #pragma unroll
            for (int jj = 0; jj < 7; ++jj) {
                const unsigned long long e2 = pack2s(ek[8 * jj]);  // LDS.32, 8 banks, bcast
                acc[jj][0] = fma2(xp0, e2, acc[jj][0]);
                acc[jj][1] = fma2(xp1, e2, acc[jj][1]);
                acc[jj][2] = fma2(xp2, e2, acc[jj][2]);
            }
        }
    }

    // ---- per-thread argmin (exact R2 compare), combine over 8 js-lanes ----
    #pragma unroll
    for (int pr = 0; pr < 3; ++pr) {
        float s0lo, s0hi, s1lo, s1hi;
        unpack2(ss0[pr], s0lo, s0hi);
        unpack2(ss1[pr], s1lo, s1hi);
        const float sxlo = s0lo + s1lo;     // row i = 2pr
        const float sxhi = s0hi + s1hi;     // row i = 2pr+1
        float vlo = 3.402823466e38f, vhi = 3.402823466e38f;
        int jlo = 0, jhi = 0;
        #pragma unroll
        for (int jj = 0; jj < 7; ++jj) {
            const int j = js + 8 * jj;
            const float sj = see[j];
            float dlo, dhi;
            unpack2(acc[jj][pr], dlo, dhi);
            float mlo = __fsub_rn(__fadd_rn(sxlo, sj), 2.0f * dlo);
            float mhi = __fsub_rn(__fadd_rn(sxhi, sj), 2.0f * dhi);
            if (mlo < vlo) { vlo = mlo; jlo = j; }
            if (mhi < vhi) { vhi = mhi; jhi = j; }
        }
        #pragma unroll
        for (int half = 0; half < 2; ++half) {
            float v = half ? vhi : vlo;
            int jx = half ? jhi : jlo;
            #pragma unroll
            for (int mask = 1; mask <= 4; mask <<= 1) {
                float ov = __shfl_xor_sync(0xffffffffu, v, mask);
                int   oj = __shfl_xor_sync(0xffffffffu, jx, mask);
                if (ov < v || (ov == v && oj < jx)) { v = ov; jx = oj; }
            }
            const int i = 2 * pr + half;
            const int grow = tile_base + warpbase + g + 4 * i;
            if (js == 0) {
                bjsh[warpbase + g + 4 * i] = jx;
                if (grow < n) out[(size_t)n * EDIM + grow] = (float)jx;
            }
        }
    }
    __syncwarp();

    // ---- phase 2: warp-cooperative coalesced straight-through write + loss ----
    float lsum = 0.f;
    const float4* e4 = reinterpret_cast<const float4*>(e);
    float4* o4 = reinterpret_cast<float4*>(out);
    #pragma unroll 4
    for (int it = 0; it < (ROWS_PER_WARP * 48) / 32; ++it) {   // 36 iters
        const int idx = it * 32 + lane;
        const int rl = idx / 48, c4 = idx - rl * 48;
        const int grow = tile_base + warpbase + rl;
        if (grow < n) {
            const int bj = bjsh[warpbase + rl];
            const float4 xq = __ldg(x4 + (size_t)grow * 48 + c4);
            const float4 qq = __ldg(e4 + (size_t)bj * 48 + c4);
            float dx = __fsub_rn(qq.x, xq.x), dy = __fsub_rn(qq.y, xq.y);
            float dz = __fsub_rn(qq.z, xq.z), dw = __fsub_rn(qq.w, xq.w);
            lsum = fmaf(dx, dx, lsum); lsum = fmaf(dy, dy, lsum);
            lsum = fmaf(dz, dz, lsum); lsum = fmaf(dw, dw, lsum);
            float4 o;
            o.x = __fadd_rn(xq.x, dx); o.y = __fadd_rn(xq.y, dy);
            o.z = __fadd_rn(xq.z, dz); o.w = __fadd_rn(xq.w, dw);
            o4[(size_t)grow * 48 + c4] = o;
        }
    }

    // ---- loss reduction + single-kernel finalize ----
    #pragma unroll
    for (int off = 16; off > 0; off >>= 1)
        lsum += __shfl_down_sync(0xffffffffu, lsum, off);
    if (lane == 0) wred[wid] = lsum;
    __syncthreads();
    if (tid == 0) {
        float bs = 0.f;
        #pragma unroll
        for (int w = 0; w < NWARP; ++w) bs += wred[w];
        atomicAdd(&g_loss_sum, (double)bs);
        __threadfence();
        unsigned int prev = atomicAdd(&g_done, 1u);
        if (prev == gridDim.x - 1) {
            __threadfence();
            double total = atomicAdd(&g_loss_sum, 0.0);
            double mean = total / ((double)n * (double)EDIM);
            out[(size_t)n * EDIM + n]     = (float)(1.25 * mean);  // (1+BETA)*mean
            out[(size_t)n * EDIM + n + 1] = 0.0f;                  // contrastloss
            g_loss_sum = 0.0;
            g_done = 0u;
            __threadfence();
        }
    }
}

extern "C" void kernel_launch(void* const* d_in, const int* in_sizes, int n_in,
                              void* d_out, int out_size) {
    (void)n_in; (void)out_size;
    const float* x = (const float*)d_in[0];   // [N, 192] fp32
    const float* e = (const float*)d_in[1];   // [50, 192] fp32
    float* out = (float*)d_out;               // [N*192 | N | 1 | 1] fp32
    const int n = in_sizes[0] / EDIM;

    const int blocks = (n + ROWS_PER_BLOCK - 1) / ROWS_PER_BLOCK;
    vq_kernel<<<blocks, NTHREADS>>>(x, e, out, n);
}

// round 9
// speedup vs baseline: 1.3796x; 1.3796x over previous
#include <cuda_runtime.h>
#include <cstdint>

#define NJ 50
#define EDIM 192
#define NJP 56
#define ETSTRIDE 56       // Et [k][j] stride (floats); j>=50 zero, see=+inf
#define NWARP 8
#define NTHREADS 256
#define RPT 4
#define ROWS_PER_WARP 32
#define ROWS_PER_BLOCK 256
#define XSTRIDE4 9        // xs row stride in float4 (8 + 1 pad)

// dynamic smem byte offsets
#define OFF_ET   0
#define OFF_XS   43008                      // 192*56*4
#define OFF_SEE  (OFF_XS + 36864)           // 256*9*16
#define OFF_BJ   (OFF_SEE + 224)
#define OFF_WRED (OFF_BJ + 1024)
#define SMEM_TOTAL (OFF_WRED + 32)          // 81184 B -> 2 CTAs/SM

__device__ double g_loss_sum;     // zero-init at module load
__device__ unsigned int g_done;

static __device__ __forceinline__ unsigned long long pack2s(float v) {
    unsigned long long r;
    asm("mov.b64 %0, {%1, %1};" : "=l"(r) : "f"(v));
    return r;
}
static __device__ __forceinline__ void unpack2(unsigned long long v, float& lo, float& hi) {
    asm("mov.b64 {%0, %1}, %2;" : "=f"(lo), "=f"(hi) : "l"(v));
}
static __device__ __forceinline__ unsigned long long fma2(unsigned long long a,
                                                          unsigned long long b,
                                                          unsigned long long c) {
    unsigned long long d;
    asm("fma.rn.f32x2 %0, %1, %2, %3;" : "=l"(d) : "l"(a), "l"(b), "l"(c));
    return d;
}

// lane = (g<<2)|js : js in [0,4) code split (j = 14*js+jj), g in [0,8).
// Thread rows: base + g + 8*i, i=0..3. acc f32x2 = CODE PAIR, e = raw LDS.64.
__global__ void __launch_bounds__(NTHREADS, 2) vq_kernel(
        const float* __restrict__ x, const float* __restrict__ e,
        float* __restrict__ out, int n) {
    extern __shared__ __align__(16) char smem[];
    float*  Et   = (float*)(smem + OFF_ET);
    float4* xs4  = (float4*)(smem + OFF_XS);
    float*  see  = (float*)(smem + OFF_SEE);
    int*    bjsh = (int*)(smem + OFF_BJ);
    float*  wred = (float*)(smem + OFF_WRED);

    const int tid = threadIdx.x;
    const int wid = tid >> 5;
    const int lane = tid & 31;
    const int js = lane & 3;
    const int g = lane >> 2;

    // ---- init: zero Et, fill [k][j] transpose, see (+inf pads) ----
    for (int i = tid; i < EDIM * ETSTRIDE; i += NTHREADS) Et[i] = 0.f;
    __syncthreads();
    for (int i = tid; i < NJ * EDIM; i += NTHREADS) {
        int j = i / EDIM, k = i - j * EDIM;        // e[j][k] coalesced
        Et[k * ETSTRIDE + j] = e[i];
    }
    if (tid < NJP) {
        float s = 3.402823466e38f;
        if (tid < NJ) {
            s = 0.f;
            const float* ej = e + (size_t)tid * EDIM;
            #pragma unroll 4
            for (int k = 0; k < EDIM; ++k) { float v = __ldg(ej + k); s = fmaf(v, v, s); }
        }
        see[tid] = s;
    }
    __syncthreads();

    const int tile_base = blockIdx.x * ROWS_PER_BLOCK;
    const int warpbase = wid * ROWS_PER_WARP;

    unsigned long long acc[RPT][7];
    float s0[RPT], s1[RPT];                        // ||x||^2: x,z -> s0 ; y,w -> s1
    #pragma unroll
    for (int i = 0; i < RPT; ++i) {
        s0[i] = 0.f; s1[i] = 0.f;
        #pragma unroll
        for (int p = 0; p < 7; ++p) acc[i][p] = 0ULL;
    }

    const float4* x4 = reinterpret_cast<const float4*>(x);
    const int ebase = 14 * js;

    // ---- main loop: 6 chunks of 8 float4-kq, x staged coalesced in smem ----
    #pragma unroll 1
    for (int ch = 0; ch < 6; ++ch) {
        const int kqb = ch * 8;
        __syncthreads();                           // xs free from previous chunk
        #pragma unroll
        for (int i = 0; i < 8; ++i) {              // 2048 float4 = 256 rows x 8
            const int idx = tid + i * NTHREADS;
            const int row = idx >> 3, kql = idx & 7;
            int gr = tile_base + row; if (gr >= n) gr = n - 1;
            xs4[row * XSTRIDE4 + kql] = __ldg(x4 + (size_t)gr * 48 + kqb + kql);
        }
        __syncthreads();

        #pragma unroll 1
        for (int kql = 0; kql < 8; ++kql) {
            const int kq = kqb + kql;
            float4 xv[RPT];
            #pragma unroll
            for (int i = 0; i < RPT; ++i)
                xv[i] = xs4[(warpbase + g + 8 * i) * XSTRIDE4 + kql];

            #pragma unroll
            for (int c = 0; c < 4; ++c) {
                const int k = kq * 4 + c;
                const unsigned long long* ep =
                    reinterpret_cast<const unsigned long long*>(&Et[k * ETSTRIDE + ebase]);
                float a0, a1, a2, a3;
                if (c == 0)      { a0=xv[0].x; a1=xv[1].x; a2=xv[2].x; a3=xv[3].x; }
                else if (c == 1) { a0=xv[0].y; a1=xv[1].y; a2=xv[2].y; a3=xv[3].y; }
                else if (c == 2) { a0=xv[0].z; a1=xv[1].z; a2=xv[2].z; a3=xv[3].z; }
                else             { a0=xv[0].w; a1=xv[1].w; a2=xv[2].w; a3=xv[3].w; }
                if ((c & 1) == 0) {
                    s0[0] = fmaf(a0, a0, s0[0]); s0[1] = fmaf(a1, a1, s0[1]);
                    s0[2] = fmaf(a2, a2, s0[2]); s0[3] = fmaf(a3, a3, s0[3]);
                } else {
                    s1[0] = fmaf(a0, a0, s1[0]); s1[1] = fmaf(a1, a1, s1[1]);
                    s1[2] = fmaf(a2, a2, s1[2]); s1[3] = fmaf(a3, a3, s1[3]);
                }
                const unsigned long long xp0 = pack2s(a0), xp1 = pack2s(a1);
                const unsigned long long xp2 = pack2s(a2), xp3 = pack2s(a3);
                #pragma unroll
                for (int p = 0; p < 7; ++p) {
                    const unsigned long long ev = ep[p];   // LDS.64: codes (2p,2p+1)
                    acc[0][p] = fma2(xp0, ev, acc[0][p]);
                    acc[1][p] = fma2(xp1, ev, acc[1][p]);
                    acc[2][p] = fma2(xp2, ev, acc[2][p]);
                    acc[3][p] = fma2(xp3, ev, acc[3][p]);
                }
            }
        }
    }

    // ---- per-thread argmin (exact R2 compare), combine over 4 js-lanes ----
    #pragma unroll
    for (int i = 0; i < RPT; ++i) {
        const float sxx = s0[i] + s1[i];
        float v = 3.402823466e38f;
        int jx = 0;
        #pragma unroll
        for (int p = 0; p < 7; ++p) {
            float dlo, dhi;
            unpack2(acc[i][p], dlo, dhi);
            const int j = ebase + 2 * p;
            float mlo = __fsub_rn(__fadd_rn(sxx, see[j]),     2.0f * dlo);
            float mhi = __fsub_rn(__fadd_rn(sxx, see[j + 1]), 2.0f * dhi);
            if (mlo < v) { v = mlo; jx = j; }
            if (mhi < v) { v = mhi; jx = j + 1; }
        }
        #pragma unroll
        for (int mask = 1; mask <= 2; mask <<= 1) {
            float ov = __shfl_xor_sync(0xffffffffu, v, mask);
            int   oj = __shfl_xor_sync(0xffffffffu, jx, mask);
            if (ov < v || (ov == v && oj < jx)) { v = ov; jx = oj; }
        }
        const int grow = tile_base + warpbase + g + 8 * i;
        if (js == 0) {
            bjsh[warpbase + g + 8 * i] = jx;
            if (grow < n) out[(size_t)n * EDIM + grow] = (float)jx;
        }
    }
    __syncwarp();

    // ---- phase 2: warp-cooperative coalesced straight-through write + loss ----
    float lsum = 0.f;
    const float4* e4 = reinterpret_cast<const float4*>(e);
    float4* o4 = reinterpret_cast<float4*>(out);
    #pragma unroll 4
    for (int it = 0; it < (ROWS_PER_WARP * 48) / 32; ++it) {   // 48 iters
        const int idx = it * 32 + lane;
        const int rl = idx / 48, c4 = idx - rl * 48;
        const int grow = tile_base + warpbase + rl;
        if (grow < n) {
            const int bj = bjsh[warpbase + rl];
            const float4 xq = __ldg(x4 + (size_t)grow * 48 + c4);
            const float4 qq = __ldg(e4 + (size_t)bj * 48 + c4);
            float dx = __fsub_rn(qq.x, xq.x), dy = __fsub_rn(qq.y, xq.y);
            float dz = __fsub_rn(qq.z, xq.z), dw = __fsub_rn(qq.w, xq.w);
            lsum = fmaf(dx, dx, lsum); lsum = fmaf(dy, dy, lsum);
            lsum = fmaf(dz, dz, lsum); lsum = fmaf(dw, dw, lsum);
            float4 o;
            o.x = __fadd_rn(xq.x, dx); o.y = __fadd_rn(xq.y, dy);
            o.z = __fadd_rn(xq.z, dz); o.w = __fadd_rn(xq.w, dw);
            o4[(size_t)grow * 48 + c4] = o;
        }
    }

    // ---- loss reduction + single-kernel finalize ----
    #pragma unroll
    for (int off = 16; off > 0; off >>= 1)
        lsum += __shfl_down_sync(0xffffffffu, lsum, off);
    if (lane == 0) wred[wid] = lsum;
    __syncthreads();
    if (tid == 0) {
        float bs = 0.f;
        #pragma unroll
        for (int w = 0; w < NWARP; ++w) bs += wred[w];
        atomicAdd(&g_loss_sum, (double)bs);
        __threadfence();
        unsigned int prev = atomicAdd(&g_done, 1u);
        if (prev == gridDim.x - 1) {
            __threadfence();
            double total = atomicAdd(&g_loss_sum, 0.0);
            double mean = total / ((double)n * (double)EDIM);
            out[(size_t)n * EDIM + n]     = (float)(1.25 * mean);  // (1+BETA)*mean
            out[(size_t)n * EDIM + n + 1] = 0.0f;                  // contrastloss
            g_loss_sum = 0.0;
            g_done = 0u;
            __threadfence();
        }
    }
}

extern "C" void kernel_launch(void* const* d_in, const int* in_sizes, int n_in,
                              void* d_out, int out_size) {
    (void)n_in; (void)out_size;
    const float* x = (const float*)d_in[0];   // [N, 192] fp32
    const float* e = (const float*)d_in[1];   // [50, 192] fp32
    float* out = (float*)d_out;               // [N*192 | N | 1 | 1] fp32
    const int n = in_sizes[0] / EDIM;

    static int configured = 0;
    if (!configured) {
        cudaFuncSetAttribute(vq_kernel, cudaFuncAttributeMaxDynamicSharedMemorySize,
                             SMEM_TOTAL);
        configured = 1;
    }
    const int blocks = (n + ROWS_PER_BLOCK - 1) / ROWS_PER_BLOCK;
    vq_kernel<<<blocks, NTHREADS, SMEM_TOTAL>>>(x, e, out, n);
}